// round 2
// baseline (speedup 1.0000x reference)
#include <cuda_runtime.h>

// PatchGram, algebraically collapsed:
//   f[cr][p]  = mean over K=C/64 consecutive channels of feat[n, cr*K+j, p]
//   g[d4][p]  = sum over 4 consecutive cr rows of f
//   out[n, layer, c*16+d4] = (1/36) * sum_p f[c][p] * g[d4][p]
//
// Register-resident channel pooling: thread t owns CPT = C/256 whole channels
// (contiguous CPT*9 floats), accumulates the 9 per-position partials in
// registers, then a shfl tree over G = K/CPT = 4 lanes finishes each pool
// group. No input staging in smem -> L1 traffic ~1x of HBM traffic.

template <int C>
__global__ __launch_bounds__(256)
void patch_gram_kernel(const float* __restrict__ feat,
                       float* __restrict__ out,
                       int layer)
{
    constexpr int K     = C / 64;       // channels per pooled group (8 or 16)
    constexpr int ELEMS = C * 9;
    constexpr int CPT   = C / 256;      // channels per thread (4 or 2)
    constexpr int G     = K / CPT;      // lanes per pool group (= 4 for both)
    static_assert(G == 4, "lane-group size");

    __shared__ float f[64 * 9];         // channel-reduced features
    __shared__ float g[16 * 9];         // 4-row group sums of f

    const int n   = blockIdx.x;
    const int tid = threadIdx.x;

    // ---- Stage 1+2 fused: load own channels, pool in registers ----
    {
        float s[9];
        #pragma unroll
        for (int p = 0; p < 9; ++p) s[p] = 0.0f;

        const float* base = feat + (size_t)n * ELEMS + tid * (CPT * 9);

        if constexpr (CPT == 4) {
            const float4* __restrict__ src = reinterpret_cast<const float4*>(base);
            #pragma unroll
            for (int k = 0; k < 9; ++k) {
                float4 v = src[k];
                s[(4 * k + 0) % 9] += v.x;
                s[(4 * k + 1) % 9] += v.y;
                s[(4 * k + 2) % 9] += v.z;
                s[(4 * k + 3) % 9] += v.w;
            }
        } else {
            const float2* __restrict__ src = reinterpret_cast<const float2*>(base);
            #pragma unroll
            for (int k = 0; k < 9; ++k) {
                float2 v = src[k];
                s[(2 * k + 0) % 9] += v.x;
                s[(2 * k + 1) % 9] += v.y;
            }
        }

        // reduce across the G=4 lanes of the pool group (consecutive lanes)
        #pragma unroll
        for (int off = 2; off >= 1; off >>= 1) {
            #pragma unroll
            for (int p = 0; p < 9; ++p)
                s[p] += __shfl_down_sync(0xffffffffu, s[p], off);
        }

        if ((tid & 3) == 0) {
            const int cr = tid >> 2;    // (tid*CPT)/K = tid/G
            constexpr float inv_k = 1.0f / (float)K;
            #pragma unroll
            for (int p = 0; p < 9; ++p)
                f[cr * 9 + p] = s[p] * inv_k;
        }
    }
    __syncthreads();

    // ---- Stage 3: 4-row group sums of f ----
    if (tid < 144) {                    // tid = d4*9 + p
        const int d4 = tid / 9;
        const int p  = tid - d4 * 9;
        const float* base = f + (4 * d4) * 9 + p;
        g[tid] = base[0] + base[9] + base[18] + base[27];
    }
    __syncthreads();

    // ---- Stage 4: 64x16 output dots over p=9, coalesced store ----
    {
        float* __restrict__ dst = out + ((size_t)n * 2 + layer) * 1024;
        constexpr float scale = 1.0f / 36.0f;   // 1/P * 1/pool4
        #pragma unroll
        for (int o = tid; o < 1024; o += 256) {
            const int c  = o >> 4;
            const int d4 = o & 15;
            const float* fr = f + c * 9;
            const float* gr = g + d4 * 9;
            float acc = 0.0f;
            #pragma unroll
            for (int p = 0; p < 9; ++p) acc = fmaf(fr[p], gr[p], acc);
            dst[o] = acc * scale;
        }
    }
}

extern "C" void kernel_launch(void* const* d_in, const int* in_sizes, int n_in,
                              void* d_out, int out_size)
{
    const float* feat0 = (const float*)d_in[0];   // [6272, 512, 3, 3]
    const float* feat1 = (const float*)d_in[1];   // [6272, 1024, 3, 3]
    float* out = (float*)d_out;                   // [6272, 2, 1024]

    const int N0 = in_sizes[0] / (512 * 9);
    const int N1 = in_sizes[1] / (1024 * 9);

    patch_gram_kernel<512><<<N0, 256>>>(feat0, out, 0);
    patch_gram_kernel<1024><<<N1, 256>>>(feat1, out, 1);
}

// round 3
// speedup vs baseline: 1.2369x; 1.2369x over previous
#include <cuda_runtime.h>
#include <cstdint>

// PatchGram, algebraically collapsed:
//   f[cr][p] = sum over K=C/64 consecutive channels of feat[n, cr*K+j, p]  (raw sum)
//   g[d4][p] = sum over 4 consecutive cr rows of f
//   out[n,layer,c*16+d4] = f[c]·g[d4] / (36*K*K)
//
// Staging: TMA bulk copy of 512-channel tiles (1 pass for C=512, 2 for C=1024).
// Pooling: float2 smem reads, compile-time %9 rotation, shfl-tree over G lanes.
// Output: 2x2 register-blocked 64x16 dot (9 smem floats per output).

struct Smem {
    float tile[512 * 9];            // 18432 B staging tile (one pass)
    float f[64 * 9];                // pooled features
    float g[16 * 9];                // 4-row group sums
    unsigned long long mbar;
};

__device__ __forceinline__ uint32_t smem_u32(const void* p) {
    return (uint32_t)__cvta_generic_to_shared(p);
}

template <int C>
__device__ __forceinline__ void per_layer(const float* __restrict__ feat,
                                          float* __restrict__ out,
                                          int layer, int n,
                                          Smem& sm, int tid)
{
    constexpr int K      = C / 64;        // channels per pool group (8 / 16)
    constexpr int PASSES = C / 512;       // 1 / 2
    constexpr int G      = K / 2;         // lanes per group (4 / 8), thread owns 2 ch
    constexpr int GPP    = 512 / K;       // groups per pass (64 / 32)
    constexpr int PASS_BYTES = 512 * 9 * 4;   // 18432

    const uint32_t mbar   = smem_u32(&sm.mbar);
    const uint32_t tile_s = smem_u32(sm.tile);

    if (tid == 0) {
        asm volatile("mbarrier.init.shared.b64 [%0], 1;" :: "r"(mbar) : "memory");
    }
    __syncthreads();

    const char* gbase = (const char*)(feat + (size_t)n * (C * 9));

    #pragma unroll
    for (int ph = 0; ph < PASSES; ++ph) {
        if (tid == 0) {
            asm volatile("mbarrier.arrive.expect_tx.shared.b64 _, [%0], %1;"
                         :: "r"(mbar), "r"(PASS_BYTES) : "memory");
            asm volatile("cp.async.bulk.shared::cta.global.mbarrier::complete_tx::bytes"
                         " [%0], [%1], %2, [%3];"
                         :: "r"(tile_s), "l"(gbase + (size_t)ph * PASS_BYTES),
                            "r"(PASS_BYTES), "r"(mbar)
                         : "memory");
        }
        // all threads wait for the tile (parity = ph)
        asm volatile(
            "{\n\t"
            ".reg .pred P1;\n\t"
            "WAIT_%=:\n\t"
            "mbarrier.try_wait.parity.acquire.cta.shared::cta.b64 P1, [%0], %1, 0x989680;\n\t"
            "@P1 bra DONE_%=;\n\t"
            "bra WAIT_%=;\n\t"
            "DONE_%=:\n\t"
            "}"
            :: "r"(mbar), "r"(ph) : "memory");

        // ---- channel pooling: thread owns channels (2*tid, 2*tid+1) of this pass ----
        {
            float s[9];
            #pragma unroll
            for (int p = 0; p < 9; ++p) s[p] = 0.0f;

            // tile float offset 18*tid + 2k ; 18*tid ≡ 0 (mod 9) -> p indices static
            const float2* __restrict__ src =
                reinterpret_cast<const float2*>(sm.tile) + tid * 9;
            #pragma unroll
            for (int k = 0; k < 9; ++k) {
                float2 v = src[k];
                s[(2 * k)     % 9] += v.x;
                s[(2 * k + 1) % 9] += v.y;
            }

            // reduce across the G consecutive lanes of this pool group
            #pragma unroll
            for (int off = G / 2; off >= 1; off >>= 1) {
                #pragma unroll
                for (int p = 0; p < 9; ++p)
                    s[p] += __shfl_down_sync(0xffffffffu, s[p], off);
            }

            if ((tid & (G - 1)) == 0) {
                const int cr = ph * GPP + tid / G;   // disjoint rows per pass
                #pragma unroll
                for (int p = 0; p < 9; ++p)
                    sm.f[cr * 9 + p] = s[p];
            }
        }
        __syncthreads();   // tile fully consumed; safe to overwrite next pass
    }

    // ---- 4-row group sums of f ----
    if (tid < 144) {                      // tid = d4*9 + p
        const int d4 = tid / 9;
        const int p  = tid - d4 * 9;
        const float* b = sm.f + (4 * d4) * 9 + p;
        sm.g[tid] = b[0] + b[9] + b[18] + b[27];
    }
    __syncthreads();

    // ---- 64x16 output dot, 2x2 register blocking ----
    {
        float* __restrict__ dst = out + ((size_t)n * 2 + layer) * 1024;
        constexpr float scale = 1.0f / (36.0f * (float)K * (float)K);

        const int c  = (tid >> 3) * 2;    // 0,2,...,62
        const int d4 = (tid & 7) * 2;     // 0,2,...,14

        const float* __restrict__ f0 = sm.f + c * 9;
        const float* __restrict__ f1 = f0 + 9;
        const float* __restrict__ g0 = sm.g + d4 * 9;
        const float* __restrict__ g1 = g0 + 9;

        float a00 = 0.f, a01 = 0.f, a10 = 0.f, a11 = 0.f;
        #pragma unroll
        for (int p = 0; p < 9; ++p) {
            const float x0 = f0[p], x1 = f1[p];
            const float y0 = g0[p], y1 = g1[p];
            a00 = fmaf(x0, y0, a00); a01 = fmaf(x0, y1, a01);
            a10 = fmaf(x1, y0, a10); a11 = fmaf(x1, y1, a11);
        }

        float2* __restrict__ d2 = reinterpret_cast<float2*>(dst);
        d2[(c * 16 + d4) >> 1]       = make_float2(a00 * scale, a01 * scale);
        d2[((c + 1) * 16 + d4) >> 1] = make_float2(a10 * scale, a11 * scale);
    }
}

__global__ __launch_bounds__(256)
void patch_gram_all(const float* __restrict__ feat0,
                    const float* __restrict__ feat1,
                    float* __restrict__ out,
                    int n0)
{
    __shared__ Smem sm;
    const int b   = blockIdx.x;
    const int tid = threadIdx.x;
    if (b < n0) per_layer<512>(feat0, out, 0, b, sm, tid);
    else        per_layer<1024>(feat1, out, 1, b - n0, sm, tid);
}

extern "C" void kernel_launch(void* const* d_in, const int* in_sizes, int n_in,
                              void* d_out, int out_size)
{
    const float* feat0 = (const float*)d_in[0];   // [6272, 512, 3, 3]
    const float* feat1 = (const float*)d_in[1];   // [6272, 1024, 3, 3]
    float* out = (float*)d_out;                   // [6272, 2, 1024]

    const int N0 = in_sizes[0] / (512 * 9);
    const int N1 = in_sizes[1] / (1024 * 9);

    patch_gram_all<<<N0 + N1, 256>>>(feat0, feat1, out, N0);
}

// round 4
// speedup vs baseline: 1.2699x; 1.0267x over previous
#include <cuda_runtime.h>
#include <cstdint>

// PatchGram, algebraically collapsed:
//   f[cr][p] = sum over K=C/64 consecutive channels of feat[n, cr*K+j, p]
//   g[d4][p] = sum over 4 consecutive cr rows of f
//   out[n,layer,c*16+d4] = f[c]·g[d4] / (36*K*K)
//
// Persistent CTAs, 2-deep TMA ring, atomic work-stealing over samples.
// Work item = sample (layer0: 1 tile of 512ch, layer1: 2 tiles of 512ch).

#define TILE_FLOATS (512 * 9)
#define TILE_BYTES  (TILE_FLOATS * 4)
#define NUM_CTAS    740

__device__ int g_work;

struct Smem {
    float tile[2][TILE_FLOATS];     // 36864 B ring
    float f[64 * 9];
    float g[16 * 9];
    unsigned long long mbar[2];
    int sq[2];                      // sample id per ring slot (-1 = sentinel)
    int pq[2];                      // pass id per ring slot
};

__device__ __forceinline__ uint32_t smem_u32(const void* p) {
    return (uint32_t)__cvta_generic_to_shared(p);
}

__device__ __forceinline__ void mbar_wait(uint32_t mbar, int parity) {
    asm volatile(
        "{\n\t"
        ".reg .pred P1;\n\t"
        "WAIT_%=:\n\t"
        "mbarrier.try_wait.parity.acquire.cta.shared::cta.b64 P1, [%0], %1, 0x989680;\n\t"
        "@P1 bra DONE_%=;\n\t"
        "bra WAIT_%=;\n\t"
        "DONE_%=:\n\t"
        "}"
        :: "r"(mbar), "r"(parity) : "memory");
}

// pool one 512-channel tile; thread owns channels (2*tid, 2*tid+1);
// G lanes per pool group; writes rows [rowbase, rowbase + 256/G).
template <int G>
__device__ __forceinline__ void pool_tile(const float* __restrict__ tile,
                                          float* __restrict__ f,
                                          int tid, int rowbase)
{
    float s[9];
    #pragma unroll
    for (int p = 0; p < 9; ++p) s[p] = 0.0f;

    // tile float offset 18*tid + 2k; 18*tid % 9 == 0 -> static rotation
    const float2* __restrict__ src = reinterpret_cast<const float2*>(tile) + tid * 9;
    #pragma unroll
    for (int k = 0; k < 9; ++k) {
        float2 v = src[k];
        s[(2 * k)     % 9] += v.x;
        s[(2 * k + 1) % 9] += v.y;
    }
    #pragma unroll
    for (int off = G / 2; off >= 1; off >>= 1) {
        #pragma unroll
        for (int p = 0; p < 9; ++p)
            s[p] += __shfl_down_sync(0xffffffffu, s[p], off);
    }
    if ((tid & (G - 1)) == 0) {
        const int cr = rowbase + tid / G;
        #pragma unroll
        for (int p = 0; p < 9; ++p)
            f[cr * 9 + p] = s[p];
    }
}

__global__ void reset_counter() { g_work = 0; }

__global__ __launch_bounds__(256)
void patch_gram_persistent(const float* __restrict__ feat0,
                           const float* __restrict__ feat1,
                           float* __restrict__ out,
                           int n0, int total)
{
    __shared__ Smem sm;
    const int tid = threadIdx.x;

    const uint32_t mb0 = smem_u32(&sm.mbar[0]);
    const uint32_t mb1 = smem_u32(&sm.mbar[1]);
    const uint32_t ts0 = smem_u32(sm.tile[0]);
    const uint32_t ts1 = smem_u32(sm.tile[1]);

    if (tid == 0) {
        asm volatile("mbarrier.init.shared.b64 [%0], 1;" :: "r"(mb0) : "memory");
        asm volatile("mbarrier.init.shared.b64 [%0], 1;" :: "r"(mb1) : "memory");
    }
    __syncthreads();

    // ---- tid0-only issue state machine ----
    int is = 0, ip = 0, inp = 0;          // issuing sample / pass / npasses
    bool need_fetch = true;

    auto issue = [&](int b) {             // tid==0 only
        if (need_fetch) {
            is = atomicAdd(&g_work, 1);
            ip = 0;
            inp = (is < n0) ? 1 : 2;
            need_fetch = false;
        }
        const uint32_t mb = b ? mb1 : mb0;
        if (is >= total) {                // out of work: sentinel arrive
            sm.sq[b] = -1;
            asm volatile("mbarrier.arrive.shared.b64 _, [%0];" :: "r"(mb) : "memory");
            return;
        }
        sm.sq[b] = is;
        sm.pq[b] = ip;
        const char* src = (is < n0)
            ? (const char*)(feat0 + (size_t)is * TILE_FLOATS)
            : (const char*)(feat1 + (size_t)(is - n0) * (2 * TILE_FLOATS) + (size_t)ip * TILE_FLOATS);
        asm volatile("mbarrier.arrive.expect_tx.shared.b64 _, [%0], %1;"
                     :: "r"(mb), "n"(TILE_BYTES) : "memory");
        asm volatile("cp.async.bulk.shared::cta.global.mbarrier::complete_tx::bytes"
                     " [%0], [%1], %2, [%3];"
                     :: "r"(b ? ts1 : ts0), "l"(src), "n"(TILE_BYTES), "r"(mb)
                     : "memory");
        if (++ip >= inp) need_fetch = true;
    };

    if (tid == 0) { issue(0); issue(1); }

    // ---- consume loop (all threads, lockstep) ----
    int consumed = 0;
    while (true) {
        const int b   = consumed & 1;
        const int par = (consumed >> 1) & 1;
        mbar_wait(b ? mb1 : mb0, par);

        const int s = sm.sq[b];
        if (s < 0) break;
        const int ph = sm.pq[b];
        const bool is_l0 = (s < n0);

        if (is_l0) pool_tile<4>(sm.tile[b], sm.f, tid, 0);        // K=8:  64 rows
        else       pool_tile<8>(sm.tile[b], sm.f, tid, ph * 32);  // K=16: 32 rows/pass
        __syncthreads();                  // tile consumed + f rows visible

        if (tid == 0) issue(b);           // refill freed slot; overlaps epilogue

        const bool last = is_l0 || (ph == 1);
        if (last) {
            // stage 3: 4-row group sums
            if (tid < 144) {              // tid = d4*9 + p
                const int d4 = tid / 9;
                const int p  = tid - d4 * 9;
                const float* bp = sm.f + (4 * d4) * 9 + p;
                sm.g[tid] = bp[0] + bp[9] + bp[18] + bp[27];
            }
            __syncthreads();

            // stage 4: 64x16 dot, 2x2 register blocking
            {
                const int n     = is_l0 ? s : (s - n0);
                const int layer = is_l0 ? 0 : 1;
                const float scale = is_l0 ? (1.0f / (36.0f * 64.0f))
                                          : (1.0f / (36.0f * 256.0f));
                float* __restrict__ dst = out + ((size_t)n * 2 + layer) * 1024;

                const int c  = (tid >> 3) * 2;
                const int d4 = (tid & 7) * 2;
                const float* __restrict__ f0 = sm.f + c * 9;
                const float* __restrict__ f1 = f0 + 9;
                const float* __restrict__ g0 = sm.g + d4 * 9;
                const float* __restrict__ g1 = g0 + 9;

                float a00 = 0.f, a01 = 0.f, a10 = 0.f, a11 = 0.f;
                #pragma unroll
                for (int p = 0; p < 9; ++p) {
                    const float x0 = f0[p], x1 = f1[p];
                    const float y0 = g0[p], y1 = g1[p];
                    a00 = fmaf(x0, y0, a00); a01 = fmaf(x0, y1, a01);
                    a10 = fmaf(x1, y0, a10); a11 = fmaf(x1, y1, a11);
                }
                float2* __restrict__ d2 = reinterpret_cast<float2*>(dst);
                d2[(c * 16 + d4) >> 1]       = make_float2(a00 * scale, a01 * scale);
                d2[((c + 1) * 16 + d4) >> 1] = make_float2(a10 * scale, a11 * scale);
            }
            __syncthreads();              // protect f/g before next pooling
        }
        ++consumed;
    }
}

extern "C" void kernel_launch(void* const* d_in, const int* in_sizes, int n_in,
                              void* d_out, int out_size)
{
    const float* feat0 = (const float*)d_in[0];   // [6272, 512, 3, 3]
    const float* feat1 = (const float*)d_in[1];   // [6272, 1024, 3, 3]
    float* out = (float*)d_out;                   // [6272, 2, 1024]

    const int N0 = in_sizes[0] / (512 * 9);
    const int N1 = in_sizes[1] / (1024 * 9);
    const int total = N0 + N1;

    reset_counter<<<1, 1>>>();
    const int grid = total < NUM_CTAS ? total : NUM_CTAS;
    patch_gram_persistent<<<grid, 256>>>(feat0, feat1, out, N0, total);
}